// round 2
// baseline (speedup 1.0000x reference)
#include <cuda_runtime.h>
#include <math.h>

#define BB 16
#define NL 48
#define NP 256
#define DD 128
#define NROW_L (BB*NL)    /* 768  */
#define NROW_P (BB*NP)    /* 4096 */
#define NPAIR  (BB*NL*NP) /* 196608 */

#define PI_OFF 0
#define SG_OFF (NPAIR*10)
#define MU_OFF (NPAIR*20)
#define DI_OFF (NPAIR*30)
#define CM_OFF (NPAIR*31)

__device__ int    g_cum_l[BB+1];
__device__ int    g_cum_p[BB+1];
__device__ float  g_u [NROW_L*DD];
__device__ float  g_eu[NROW_L*DD];
__device__ float2 g_w [BB*DD*NP];   // [b][d][p] packed {v, exp(v)}
__device__ float4 g_xl[NROW_L];     // x,y,z,|x|^2 (zeros if masked)
__device__ float4 g_xp[NROW_P];

// -------- prep: prefix sums + dense position scatter --------
__global__ void k_prep(const int* __restrict__ num_l, const int* __restrict__ num_p,
                       const float* __restrict__ pos_l, const float* __restrict__ pos_p)
{
    __shared__ int cl[BB+1], cp[BB+1];
    int tid = threadIdx.x;
    if (tid == 0) {
        cl[0] = 0; cp[0] = 0;
        for (int i = 0; i < BB; i++) { cl[i+1] = cl[i] + num_l[i]; cp[i+1] = cp[i] + num_p[i]; }
        for (int i = 0; i <= BB; i++) { g_cum_l[i] = cl[i]; g_cum_p[i] = cp[i]; }
    }
    __syncthreads();
    for (int r = tid; r < NROW_L; r += blockDim.x) {
        int b = r / NL, l = r % NL;
        float4 o = make_float4(0.f, 0.f, 0.f, 0.f);
        if (l < num_l[b]) {
            int s = cl[b] + l;
            float x = pos_l[s*3+0], y = pos_l[s*3+1], z = pos_l[s*3+2];
            o = make_float4(x, y, z, x*x + y*y + z*z);
        }
        g_xl[r] = o;
    }
    for (int r = tid; r < NROW_P; r += blockDim.x) {
        int b = r / NP, p = r % NP;
        float4 o = make_float4(0.f, 0.f, 0.f, 0.f);
        if (p < num_p[b]) {
            int s = cp[b] + p;
            float x = pos_p[s*3+0], y = pos_p[s*3+1], z = pos_p[s*3+2];
            o = make_float4(x, y, z, x*x + y*y + z*z);
        }
        g_xp[r] = o;
    }
}

// -------- u = (hl@W1a + b1 - mean)*k + beta; eu = exp(u). 8 rows/block --------
__global__ void k_u(const float* __restrict__ hl, const float* __restrict__ W1,
                    const float* __restrict__ b1, const float* __restrict__ gamma,
                    const float* __restrict__ beta, const float* __restrict__ mean,
                    const float* __restrict__ var, const int* __restrict__ num_l)
{
    __shared__ float xs[8][DD];
    int f = threadIdx.x;
    int r0 = blockIdx.x * 8;
    #pragma unroll
    for (int i = 0; i < 8; i++) {
        int r = r0 + i, b = r / NL, l = r % NL;
        float v = 0.f;
        if (l < num_l[b]) v = hl[(g_cum_l[b] + l) * DD + f];
        xs[i][f] = v;
    }
    __syncthreads();
    float acc[8] = {0.f,0.f,0.f,0.f,0.f,0.f,0.f,0.f};
    #pragma unroll 4
    for (int d = 0; d < DD; d++) {
        float w = W1[d * DD + f];
        #pragma unroll
        for (int i = 0; i < 8; i++) acc[i] = fmaf(xs[i][d], w, acc[i]);
    }
    float k = gamma[f] * rsqrtf(var[f] + 1e-5f);
    float c = (b1[f] - mean[f]) * k + beta[f];
    #pragma unroll
    for (int i = 0; i < 8; i++) {
        float u = fmaf(acc[i], k, c);
        g_u [(r0 + i) * DD + f] = u;
        g_eu[(r0 + i) * DD + f] = __expf(u);
    }
}

// -------- v = (hp@W1b)*k; store transposed packed {v, exp(v)}. 8 rows/block --------
__global__ void k_v(const float* __restrict__ hp, const float* __restrict__ W1,
                    const float* __restrict__ gamma, const float* __restrict__ var,
                    const int* __restrict__ num_p)
{
    __shared__ float xs[8][DD];
    int f = threadIdx.x;
    int r0 = blockIdx.x * 8;
    #pragma unroll
    for (int i = 0; i < 8; i++) {
        int r = r0 + i, b = r / NP, p = r % NP;
        float v = 0.f;
        if (p < num_p[b]) v = hp[(g_cum_p[b] + p) * DD + f];
        xs[i][f] = v;
    }
    __syncthreads();
    float acc[8] = {0.f,0.f,0.f,0.f,0.f,0.f,0.f,0.f};
    const float* W1b = W1 + DD * DD;
    #pragma unroll 4
    for (int d = 0; d < DD; d++) {
        float w = W1b[d * DD + f];
        #pragma unroll
        for (int i = 0; i < 8; i++) acc[i] = fmaf(xs[i][d], w, acc[i]);
    }
    float k = gamma[f] * rsqrtf(var[f] + 1e-5f);
    #pragma unroll
    for (int i = 0; i < 8; i++) {
        int r = r0 + i, b = r / NP, p = r % NP;
        float v = acc[i] * k;
        g_w[(b * DD + f) * NP + p] = make_float2(v, __expf(v));
    }
}

// -------- main: one block per (b,l), one thread per p --------
__global__ __launch_bounds__(NP) void k_main(
    const float* __restrict__ W_pi, const float* __restrict__ b_pi,
    const float* __restrict__ W_sg, const float* __restrict__ b_sg,
    const float* __restrict__ W_mu, const float* __restrict__ b_mu,
    const int* __restrict__ num_l, const int* __restrict__ num_p,
    float* __restrict__ out)
{
    __shared__ float u_s[DD], eu_s[DD];
    __shared__ float Ws[DD * 32];     // [d][j]: j<10 pi, 10..19 sigma, 20..29 mu
    __shared__ float bias[32];

    const int tid = threadIdx.x;
    const int bl  = blockIdx.x;
    const int b   = bl / NL;
    const int l   = bl % NL;

    if (tid < DD) {
        u_s [tid] = g_u [bl * DD + tid];
        eu_s[tid] = g_eu[bl * DD + tid];
    }
    for (int idx = tid; idx < DD * 10; idx += NP) {
        int d = idx / 10, j = idx % 10;
        Ws[d * 32 + j     ] = W_pi[idx];
        Ws[d * 32 + 10 + j] = W_sg[idx];
        Ws[d * 32 + 20 + j] = W_mu[idx];
    }
    if (tid < 10) {
        bias[tid     ] = b_pi[tid];
        bias[tid + 10] = b_sg[tid];
        bias[tid + 20] = b_mu[tid];
    }
    __syncthreads();

    const int p = tid;
    const float m = (l < num_l[b] && p < num_p[b]) ? 1.f : 0.f;

    float acc[30];
    #pragma unroll
    for (int j = 0; j < 30; j++) acc[j] = 0.f;

    const float2* __restrict__ wrow = g_w + (size_t)(b * DD) * NP + p;

    #pragma unroll 4
    for (int d = 0; d < DD; d++) {
        float2 w  = wrow[d * NP];
        float  uv = u_s[d] + w.x;
        float  e  = (uv > 0.f) ? uv : fmaf(eu_s[d], w.y, -1.f);  // elu via exp(u)*exp(v)-1
        const float* wp = &Ws[d * 32];
        #pragma unroll
        for (int j = 0; j < 30; j++) acc[j] = fmaf(e, wp[j], acc[j]);
    }

    // softmax over pi (j=0..9)
    float zmax = -1e30f;
    #pragma unroll
    for (int j = 0; j < 10; j++) { acc[j] += bias[j]; zmax = fmaxf(zmax, acc[j]); }
    float ssum = 0.f;
    #pragma unroll
    for (int j = 0; j < 10; j++) { float e = __expf(acc[j] - zmax); acc[j] = e; ssum += e; }
    float inv = m / ssum;

    const int base = (bl * NP + p) * 10;
    #pragma unroll
    for (int j = 0; j < 10; j++) out[PI_OFF + base + j] = acc[j] * inv;

    #pragma unroll
    for (int j = 0; j < 10; j++) {
        float z = acc[10 + j] + bias[10 + j];
        float e = (z > 0.f) ? z : (__expf(z) - 1.f);
        out[SG_OFF + base + j] = (e + 1.1f) * m;
    }
    #pragma unroll
    for (int j = 0; j < 10; j++) {
        float z = acc[20 + j] + bias[20 + j];
        float e = (z > 0.f) ? z : (__expf(z) - 1.f);
        out[MU_OFF + base + j] = (e + 1.0f) * m;
    }

    // distance + mask
    float4 xl = g_xl[bl];
    float4 xp = g_xp[b * NP + p];
    float d2 = xl.w + xp.w - 2.f * (xl.x * xp.x + xl.y * xp.y + xl.z * xp.z);
    out[DI_OFF + bl * NP + p] = sqrtf(fmaxf(d2, 0.f)) * m;
    out[CM_OFF + bl * NP + p] = m;
}

extern "C" void kernel_launch(void* const* d_in, const int* in_sizes, int n_in,
                              void* d_out, int out_size)
{
    // inputs: hl hp pos_l pos_p num_l num_p [n_l_max n_p_max] W1 b1 gamma beta
    //         run_mean run_var W_pi b_pi W_sigma b_sigma W_mu b_mu
    int s = 0;
    if (n_in >= 20 && in_sizes[6] == 1 && in_sizes[7] == 1) s = 2;

    const float* hl    = (const float*)d_in[0];
    const float* hp    = (const float*)d_in[1];
    const float* pos_l = (const float*)d_in[2];
    const float* pos_p = (const float*)d_in[3];
    const int*   num_l = (const int*)  d_in[4];
    const int*   num_p = (const int*)  d_in[5];
    const float* W1    = (const float*)d_in[6 + s];
    const float* b1    = (const float*)d_in[7 + s];
    const float* gamma = (const float*)d_in[8 + s];
    const float* beta  = (const float*)d_in[9 + s];
    const float* mean  = (const float*)d_in[10 + s];
    const float* var   = (const float*)d_in[11 + s];
    const float* W_pi  = (const float*)d_in[12 + s];
    const float* b_pi  = (const float*)d_in[13 + s];
    const float* W_sg  = (const float*)d_in[14 + s];
    const float* b_sg  = (const float*)d_in[15 + s];
    const float* W_mu  = (const float*)d_in[16 + s];
    const float* b_mu  = (const float*)d_in[17 + s];
    float* out = (float*)d_out;

    k_prep<<<1, 512>>>(num_l, num_p, pos_l, pos_p);
    k_u<<<NROW_L / 8, DD>>>(hl, W1, b1, gamma, beta, mean, var, num_l);
    k_v<<<NROW_P / 8, DD>>>(hp, W1, gamma, var, num_p);
    k_main<<<BB * NL, NP>>>(W_pi, b_pi, W_sg, b_sg, W_mu, b_mu, num_l, num_p, out);
}

// round 3
// speedup vs baseline: 1.2596x; 1.2596x over previous
#include <cuda_runtime.h>
#include <math.h>

#define BB 16
#define NL 48
#define NP 256
#define DD 128
#define NROW_L (BB*NL)    /* 768  */
#define NROW_P (BB*NP)    /* 4096 */
#define NPAIR  (BB*NL*NP) /* 196608 */

#define PI_OFF 0
#define SG_OFF (NPAIR*10)
#define MU_OFF (NPAIR*20)
#define DI_OFF (NPAIR*30)
#define CM_OFF (NPAIR*31)

__device__ float2 g_ueu[NROW_L*DD];   // {u, exp(u)} per (b,l,d)
__device__ float2 g_w  [BB*DD*NP];    // [b][d][p] packed {v, exp(v)}
__device__ float4 g_xl [NROW_L];      // x,y,z,|x|^2 (zeros if masked)
__device__ float4 g_xp [NROW_P];

// ---------------- PTX helpers (f32x2 packed FMA path) ----------------
__device__ __forceinline__ unsigned long long pk2(float x) {
    unsigned long long r;
    asm("mov.b64 %0, {%1, %1};" : "=l"(r) : "f"(x));
    return r;
}
#define FFMA2(acc, a, b) \
    asm volatile("fma.rn.f32x2 %0, %1, %2, %0;" : "+l"(acc) : "l"(a), "l"(b))
#define LDSV2(lo, hi, addr, IMM) \
    asm volatile("ld.shared.v2.b64 {%0, %1}, [%2+" IMM "];" \
                 : "=l"(lo), "=l"(hi) : "r"(addr))
#define UNPK(lo, hi, v) \
    asm("mov.b64 {%0, %1}, %2;" : "=f"(lo), "=f"(hi) : "l"(v))

__device__ __forceinline__ unsigned smem_u32(const void* p) {
    return (unsigned)__cvta_generic_to_shared(p);
}

// ---------------- fused prep: u/eu rows, w table, positions ----------------
// blocks 0..95: l-side (8 rows each).  blocks 96..607: p-side (8 rows each).
__global__ __launch_bounds__(DD) void k_pre(
    const float* __restrict__ hl, const float* __restrict__ hp,
    const float* __restrict__ pos_l, const float* __restrict__ pos_p,
    const int* __restrict__ num_l, const int* __restrict__ num_p,
    const float* __restrict__ W1, const float* __restrict__ b1,
    const float* __restrict__ gamma, const float* __restrict__ beta,
    const float* __restrict__ mean, const float* __restrict__ var)
{
    __shared__ int cl[BB+1], cp[BB+1];
    __shared__ float xs[8][DD];
    __shared__ float2 tt[DD][9];   // transpose tile (v-side), padded
    const int tid = threadIdx.x;

    if (tid == 0) {
        cl[0] = 0; cp[0] = 0;
        #pragma unroll
        for (int i = 0; i < BB; i++) { cl[i+1] = cl[i] + num_l[i]; cp[i+1] = cp[i] + num_p[i]; }
    }
    __syncthreads();

    const float kf = gamma[tid] * rsqrtf(var[tid] + 1e-5f);

    if (blockIdx.x < NROW_L/8) {
        // ---- l side ----
        const int r0 = blockIdx.x * 8;
        const int b  = r0 / NL, l0 = r0 % NL;
        const int nl = num_l[b];
        #pragma unroll
        for (int i = 0; i < 8; i++) {
            float v = 0.f;
            if (l0 + i < nl) v = hl[(cl[b] + l0 + i) * DD + tid];
            xs[i][tid] = v;
        }
        __syncthreads();
        float acc[8] = {0,0,0,0,0,0,0,0};
        #pragma unroll 4
        for (int d = 0; d < DD; d++) {
            float w = W1[d * DD + tid];
            #pragma unroll
            for (int i = 0; i < 8; i++) acc[i] = fmaf(xs[i][d], w, acc[i]);
        }
        const float c = (b1[tid] - mean[tid]) * kf + beta[tid];
        #pragma unroll
        for (int i = 0; i < 8; i++) {
            float u = fmaf(acc[i], kf, c);
            g_ueu[(r0 + i) * DD + tid] = make_float2(u, __expf(u));
        }
        if (tid < 8) {
            int l = l0 + tid;
            float4 o = make_float4(0.f, 0.f, 0.f, 0.f);
            if (l < nl) {
                int s = cl[b] + l;
                float x = pos_l[s*3+0], y = pos_l[s*3+1], z = pos_l[s*3+2];
                o = make_float4(x, y, z, x*x + y*y + z*z);
            }
            g_xl[r0 + tid] = o;
        }
    } else {
        // ---- p side ----
        const int r0 = (blockIdx.x - NROW_L/8) * 8;
        const int b  = r0 / NP, p0 = r0 % NP;
        const int np = num_p[b];
        #pragma unroll
        for (int i = 0; i < 8; i++) {
            float v = 0.f;
            if (p0 + i < np) v = hp[(cp[b] + p0 + i) * DD + tid];
            xs[i][tid] = v;
        }
        __syncthreads();
        float acc[8] = {0,0,0,0,0,0,0,0};
        const float* W1b = W1 + DD * DD;
        #pragma unroll 4
        for (int d = 0; d < DD; d++) {
            float w = W1b[d * DD + tid];
            #pragma unroll
            for (int i = 0; i < 8; i++) acc[i] = fmaf(xs[i][d], w, acc[i]);
        }
        #pragma unroll
        for (int i = 0; i < 8; i++) {
            float v = acc[i] * kf;
            tt[tid][i] = make_float2(v, __expf(v));
        }
        __syncthreads();
        // coalesced-ish write of the transpose tile
        #pragma unroll
        for (int it = 0; it < 8; it++) {
            int idx = tid + DD * it;     // 0..1023
            int f = idx >> 3, pl = idx & 7;
            g_w[(b * DD + f) * NP + p0 + pl] = tt[f][pl];
        }
        if (tid < 8) {
            int p = p0 + tid;
            float4 o = make_float4(0.f, 0.f, 0.f, 0.f);
            if (p < np) {
                int s = cp[b] + p;
                float x = pos_p[s*3+0], y = pos_p[s*3+1], z = pos_p[s*3+2];
                o = make_float4(x, y, z, x*x + y*y + z*z);
            }
            g_xp[r0 + tid] = o;
        }
    }
}

// ---------------- epilogue for one (l,p) given 15 packed accumulators ----------------
__device__ __forceinline__ void epi(
    const unsigned long long* acc, const float* bias, float m,
    int bl, int p, float* __restrict__ out)
{
    float z[30];
    #pragma unroll
    for (int jj = 0; jj < 15; jj++) UNPK(z[2*jj], z[2*jj+1], acc[jj]);

    // softmax over pi (z[0..9])
    float zmax = -1e30f;
    #pragma unroll
    for (int j = 0; j < 10; j++) { z[j] += bias[j]; zmax = fmaxf(zmax, z[j]); }
    float ssum = 0.f;
    #pragma unroll
    for (int j = 0; j < 10; j++) { float e = __expf(z[j] - zmax); z[j] = e; ssum += e; }
    float inv = m / ssum;

    const int base = (bl * NP + p) * 10;
    float2* opi = (float2*)(out + PI_OFF + base);
    float2* osg = (float2*)(out + SG_OFF + base);
    float2* omu = (float2*)(out + MU_OFF + base);
    #pragma unroll
    for (int j = 0; j < 5; j++)
        opi[j] = make_float2(z[2*j] * inv, z[2*j+1] * inv);
    #pragma unroll
    for (int j = 0; j < 10; j++) {
        float t = z[10 + j] + bias[10 + j];
        float e = (t > 0.f) ? t : (__expf(t) - 1.f);
        z[10 + j] = (e + 1.1f) * m;
    }
    #pragma unroll
    for (int j = 0; j < 5; j++) osg[j] = make_float2(z[10+2*j], z[11+2*j]);
    #pragma unroll
    for (int j = 0; j < 10; j++) {
        float t = z[20 + j] + bias[20 + j];
        float e = (t > 0.f) ? t : (__expf(t) - 1.f);
        z[20 + j] = (e + 1.0f) * m;
    }
    #pragma unroll
    for (int j = 0; j < 5; j++) omu[j] = make_float2(z[20+2*j], z[21+2*j]);
}

// ---------------- main: one block per 2 l-rows, one thread per p ----------------
__global__ __launch_bounds__(NP, 3) void k_main(
    const float* __restrict__ W_pi, const float* __restrict__ b_pi,
    const float* __restrict__ W_sg, const float* __restrict__ b_sg,
    const float* __restrict__ W_mu, const float* __restrict__ b_mu,
    const int* __restrict__ num_l, const int* __restrict__ num_p,
    float* __restrict__ out)
{
    __shared__ float2 ueu[2][DD];     // {u, exp(u)} for the 2 l rows
    __shared__ float2 Wsp[DD][16];    // [d][jj] = {W[2jj], W[2jj+1]}, jj<15 used
    __shared__ float  bias[32];

    const int tid = threadIdx.x;
    const int bl0 = blockIdx.x * 2;   // 48 even -> both rows in same batch
    const int b   = bl0 / NL;
    const int l0  = bl0 % NL;

    {
        int l = tid >> 7, d = tid & (DD-1);
        ueu[l][d] = g_ueu[(bl0 + l) * DD + d];
    }
    for (int idx = tid; idx < DD * 15; idx += NP) {
        int d = idx / 15, jj = idx % 15;
        float a, bv;
        if (jj < 5)       { a = W_pi[d*10 + 2*jj];      bv = W_pi[d*10 + 2*jj + 1]; }
        else if (jj < 10) { a = W_sg[d*10 + 2*(jj-5)];  bv = W_sg[d*10 + 2*(jj-5) + 1]; }
        else              { a = W_mu[d*10 + 2*(jj-10)]; bv = W_mu[d*10 + 2*(jj-10) + 1]; }
        Wsp[d][jj] = make_float2(a, bv);
    }
    if (tid < 10) {
        bias[tid     ] = b_pi[tid];
        bias[tid + 10] = b_sg[tid];
        bias[tid + 20] = b_mu[tid];
    }
    __syncthreads();

    const int p = tid;
    const int mp = (p < num_p[b]);
    const int nl = num_l[b];
    const float m0 = (l0     < nl && mp) ? 1.f : 0.f;
    const float m1 = (l0 + 1 < nl && mp) ? 1.f : 0.f;

    unsigned long long acc0[15], acc1[15];
    #pragma unroll
    for (int jj = 0; jj < 15; jj++) { acc0[jj] = 0ull; acc1[jj] = 0ull; }

    const float2* __restrict__ wrow = g_w + (size_t)(b * DD) * NP + p;
    const unsigned wbase = smem_u32(&Wsp[0][0]);
    const unsigned ubase = smem_u32(&ueu[0][0]);

    #pragma unroll 4
    for (int d = 0; d < DD; d++) {
        float2 w = wrow[d * NP];                  // LDG.64 {v, exp(v)}
        float2 a0, a1;                            // LDS.64 broadcast
        asm("ld.shared.v2.f32 {%0,%1}, [%2];" : "=f"(a0.x), "=f"(a0.y) : "r"(ubase + d*8));
        asm("ld.shared.v2.f32 {%0,%1}, [%2];" : "=f"(a1.x), "=f"(a1.y) : "r"(ubase + DD*8 + d*8));
        float uv0 = a0.x + w.x, t0 = fmaf(a0.y, w.y, -1.f);
        float uv1 = a1.x + w.x, t1 = fmaf(a1.y, w.y, -1.f);
        float e0 = (uv0 > 0.f) ? uv0 : t0;
        float e1 = (uv1 > 0.f) ? uv1 : t1;
        unsigned long long e0p = pk2(e0), e1p = pk2(e1);

        const unsigned wa = wbase + d * 128;      // 16 float2 = 128B per row
        unsigned long long q0, q1;
        LDSV2(q0, q1, wa, "0");
        FFMA2(acc0[0], e0p, q0); FFMA2(acc1[0], e1p, q0);
        FFMA2(acc0[1], e0p, q1); FFMA2(acc1[1], e1p, q1);
        LDSV2(q0, q1, wa, "16");
        FFMA2(acc0[2], e0p, q0); FFMA2(acc1[2], e1p, q0);
        FFMA2(acc0[3], e0p, q1); FFMA2(acc1[3], e1p, q1);
        LDSV2(q0, q1, wa, "32");
        FFMA2(acc0[4], e0p, q0); FFMA2(acc1[4], e1p, q0);
        FFMA2(acc0[5], e0p, q1); FFMA2(acc1[5], e1p, q1);
        LDSV2(q0, q1, wa, "48");
        FFMA2(acc0[6], e0p, q0); FFMA2(acc1[6], e1p, q0);
        FFMA2(acc0[7], e0p, q1); FFMA2(acc1[7], e1p, q1);
        LDSV2(q0, q1, wa, "64");
        FFMA2(acc0[8], e0p, q0); FFMA2(acc1[8], e1p, q0);
        FFMA2(acc0[9], e0p, q1); FFMA2(acc1[9], e1p, q1);
        LDSV2(q0, q1, wa, "80");
        FFMA2(acc0[10], e0p, q0); FFMA2(acc1[10], e1p, q0);
        FFMA2(acc0[11], e0p, q1); FFMA2(acc1[11], e1p, q1);
        LDSV2(q0, q1, wa, "96");
        FFMA2(acc0[12], e0p, q0); FFMA2(acc1[12], e1p, q0);
        FFMA2(acc0[13], e0p, q1); FFMA2(acc1[13], e1p, q1);
        LDSV2(q0, q1, wa, "112");
        FFMA2(acc0[14], e0p, q0); FFMA2(acc1[14], e1p, q0);
        (void)q1;
    }

    epi(acc0, bias, m0, bl0,     p, out);
    epi(acc1, bias, m1, bl0 + 1, p, out);

    // distances + mask
    float4 xp = g_xp[b * NP + p];
    {
        float4 xl = g_xl[bl0];
        float d2 = xl.w + xp.w - 2.f * (xl.x*xp.x + xl.y*xp.y + xl.z*xp.z);
        out[DI_OFF + bl0 * NP + p] = sqrtf(fmaxf(d2, 0.f)) * m0;
        out[CM_OFF + bl0 * NP + p] = m0;
    }
    {
        float4 xl = g_xl[bl0 + 1];
        float d2 = xl.w + xp.w - 2.f * (xl.x*xp.x + xl.y*xp.y + xl.z*xp.z);
        out[DI_OFF + (bl0+1) * NP + p] = sqrtf(fmaxf(d2, 0.f)) * m1;
        out[CM_OFF + (bl0+1) * NP + p] = m1;
    }
}

extern "C" void kernel_launch(void* const* d_in, const int* in_sizes, int n_in,
                              void* d_out, int out_size)
{
    int s = 0;
    if (n_in >= 20 && in_sizes[6] == 1 && in_sizes[7] == 1) s = 2;

    const float* hl    = (const float*)d_in[0];
    const float* hp    = (const float*)d_in[1];
    const float* pos_l = (const float*)d_in[2];
    const float* pos_p = (const float*)d_in[3];
    const int*   num_l = (const int*)  d_in[4];
    const int*   num_p = (const int*)  d_in[5];
    const float* W1    = (const float*)d_in[6 + s];
    const float* b1    = (const float*)d_in[7 + s];
    const float* gamma = (const float*)d_in[8 + s];
    const float* beta  = (const float*)d_in[9 + s];
    const float* mean  = (const float*)d_in[10 + s];
    const float* var   = (const float*)d_in[11 + s];
    const float* W_pi  = (const float*)d_in[12 + s];
    const float* b_pi  = (const float*)d_in[13 + s];
    const float* W_sg  = (const float*)d_in[14 + s];
    const float* b_sg  = (const float*)d_in[15 + s];
    const float* W_mu  = (const float*)d_in[16 + s];
    const float* b_mu  = (const float*)d_in[17 + s];
    float* out = (float*)d_out;

    k_pre <<<NROW_L/8 + NROW_P/8, DD>>>(hl, hp, pos_l, pos_p, num_l, num_p,
                                        W1, b1, gamma, beta, mean, var);
    k_main<<<BB * NL / 2, NP>>>(W_pi, b_pi, W_sg, b_sg, W_mu, b_mu,
                                num_l, num_p, out);
}